// round 9
// baseline (speedup 1.0000x reference)
#include <cuda_runtime.h>
#include <cuda_fp16.h>

#define NN 50000
#define FF 16
#define EE 800000
#define HH 64
#define TOUT 10
#define NF (NN*FF)
#define NBIN 1024

// edge kernel geometry: warp per node, 8 warps/block
#define ETHR 256
#define EBLK (NN/8)            // 6250
// node kernel geometry: 16 warps/block, 4 nodes per warp (interleaved)
#define NTHRN 512
#define NPB 64                 // nodes per block
#define NBLKN ((NN + NPB - 1)/NPB)  // 782

// ---------------- device state ----------------
__device__ float   g_x0[NF];
__device__ float   g_xi[NF];
__device__ float   g_k[6][NF];
__device__ __half2 g_uv[2][NN*32];   // packed u: (.x=ch lane, .y=ch lane+32), double-buffered
__device__ float   g_v[NN*HH];
__device__ float   g_agg[NN*FF];
__device__ float   g_augproj[NN*HH];
__device__ float   g_ys[TOUT*NF];
__device__ int     g_deg[NN];
__device__ int     g_rowptr[NN+1];
__device__ int     g_wptr[NN];
__device__ int     g_src_sorted[EE];
__device__ float4  g_ea_sorted[EE];
__device__ int     g_dbin[NBIN];
__device__ int     g_dwptr[NBIN];
__device__ int     g_nodes_sorted[NN];

// DOPRI5 coefficients. Row 0 unused, rows 1..5 = A[0..4], row 6 = B.
__constant__ float c_coef[7][6] = {
  {0.f,0.f,0.f,0.f,0.f,0.f},
  {(float)(0.2), 0.f,0.f,0.f,0.f,0.f},
  {(float)(3.0/40.0), (float)(9.0/40.0), 0.f,0.f,0.f,0.f},
  {(float)(44.0/45.0), (float)(-56.0/15.0), (float)(32.0/9.0), 0.f,0.f,0.f},
  {(float)(19372.0/6561.0), (float)(-25360.0/2187.0), (float)(64448.0/6561.0), (float)(-212.0/729.0), 0.f,0.f},
  {(float)(9017.0/3168.0), (float)(-355.0/33.0), (float)(46732.0/5247.0), (float)(49.0/176.0), (float)(-5103.0/18656.0), 0.f},
  {(float)(35.0/384.0), 0.f, (float)(500.0/1113.0), (float)(125.0/192.0), (float)(-2187.0/6784.0), (float)(11.0/84.0)}
};
__constant__ float c_C[6] = {0.f, 0.2f, 0.3f, 0.8f, (float)(8.0/9.0), 1.f};

__device__ __forceinline__ float tanha(float x) {
  float r;
  asm("tanh.approx.f32 %0, %1;" : "=f"(r) : "f"(x));
  return r;
}

// ---------------- setup kernels ----------------

__global__ __launch_bounds__(256) void init_kernel(
    const float* __restrict__ xh,
    const float* __restrict__ W1m, const float* __restrict__ b1m)
{
  __shared__ float sW[32 * 64];
  __shared__ float sb[64];
  __shared__ float sxi[8][16];
  int tid = threadIdx.x;
  int gid = blockIdx.x * 256 + tid;
  if (gid < NN) g_deg[gid] = 0;
  if (gid < NBIN) g_dbin[gid] = 0;
  #pragma unroll
  for (int i = tid; i < 512; i += 256) ((float4*)sW)[i] = ((const float4*)W1m)[i];
  if (tid < 16) ((float4*)sb)[tid] = ((const float4*)b1m)[tid];
  int w = tid >> 5, lane = tid & 31;
  int n = blockIdx.x * 8 + w;
  if (n < NN) {
    if (lane < 16) {
      int idx = n * 16 + lane;
      float xv = xh[9 * NF + idx];
      g_x0[idx] = xv;
      g_xi[idx] = xv;
      sxi[w][lane] = xv;
    }
  }
  __syncthreads();
  if (n >= NN) return;
  float u0 = 0.f, u1 = 0.f;
  float v0 = sb[lane], v1 = sb[32 + lane];
  #pragma unroll
  for (int i = 0; i < 16; i++) {
    float xv = sxi[w][i];
    u0 += xv * sW[i * 64 + lane];
    u1 += xv * sW[i * 64 + 32 + lane];
    v0 += xv * sW[(16 + i) * 64 + lane];
    v1 += xv * sW[(16 + i) * 64 + 32 + lane];
  }
  g_uv[0][n * 32 + lane] = __floats2half2_rn(u0, u1);
  g_v[n * 64 + lane] = v0;
  g_v[n * 64 + 32 + lane] = v1;
}

__global__ __launch_bounds__(256) void augproj_kernel(
    const float* __restrict__ xh, const float* __restrict__ xm,
    const float* __restrict__ W1n, const float* __restrict__ b1n)
{
  __shared__ float saug[4][176];
  int tid = threadIdx.x;
  int ln = tid >> 6;
  int ch = tid & 63;
  int n = blockIdx.x * 4 + ln;
  if (ch < 16) {
    int f = ch;
    float xs[10], ms[10];
    float sm = 0.f, cm = 0.f;
    #pragma unroll
    for (int tt = 0; tt < 10; tt++) {
      xs[tt] = xh[(tt * NN + n) * FF + f];
      ms[tt] = xm[tt * NN + n];
      sm += xs[tt] * ms[tt];
      cm += ms[tt];
    }
    float cnt = fmaxf(cm, 1.0f);
    float mean = sm / cnt;
    float var = 0.f;
    #pragma unroll
    for (int tt = 0; tt < 10; tt++) { float d = xs[tt] - mean; var += d * d * ms[tt]; }
    var /= cnt;
    #pragma unroll
    for (int tt = 0; tt < 9; tt++)
      saug[ln][tt * 16 + f] = (xs[tt + 1] - xs[tt]) * (ms[tt + 1] * ms[tt]);
    saug[ln][144 + f] = mean;
    saug[ln][160 + f] = var;
  }
  __syncthreads();
  float acc = b1n[ch];
  #pragma unroll 8
  for (int r = 0; r < 176; r++)
    acc += saug[ln][r] * W1n[(32 + r) * 64 + ch];
  g_augproj[n * 64 + ch] = acc;
}

__global__ __launch_bounds__(256) void hist_kernel(const int* __restrict__ ei) {
  int e = blockIdx.x * 256 + threadIdx.x;
  if (e < EE) atomicAdd(&g_deg[ei[EE + e]], 1);
}

__global__ __launch_bounds__(1024) void scan_kernel() {
  __shared__ int wsum[32];
  int tid = threadIdx.x, lane = tid & 31, wid = tid >> 5;
  int carry = 0;
  for (int base = 0; base < NN; base += 1024) {
    int i = base + tid;
    int v = (i < NN) ? g_deg[i] : 0;
    int x = v;
    #pragma unroll
    for (int o = 1; o < 32; o <<= 1) { int y = __shfl_up_sync(0xffffffffu, x, o); if (lane >= o) x += y; }
    if (lane == 31) wsum[wid] = x;
    __syncthreads();
    if (wid == 0) {
      int s = wsum[lane];
      #pragma unroll
      for (int o = 1; o < 32; o <<= 1) { int y = __shfl_up_sync(0xffffffffu, s, o); if (lane >= o) s += y; }
      wsum[lane] = s;
    }
    __syncthreads();
    int incl = x + carry + (wid > 0 ? wsum[wid - 1] : 0);
    if (i < NN) { g_rowptr[i + 1] = incl; g_wptr[i] = incl - v; }
    carry += wsum[31];
    __syncthreads();
  }
  if (tid == 0) g_rowptr[0] = 0;
  __syncthreads();
  for (int n = tid; n < NN; n += 1024) {
    int d = g_deg[n]; if (d > NBIN - 1) d = NBIN - 1;
    atomicAdd(&g_dbin[(NBIN - 1) - d], 1);
  }
  __syncthreads();
  {
    int v = __ldcg(&g_dbin[tid]);
    int x = v;
    #pragma unroll
    for (int o = 1; o < 32; o <<= 1) { int y = __shfl_up_sync(0xffffffffu, x, o); if (lane >= o) x += y; }
    if (lane == 31) wsum[wid] = x;
    __syncthreads();
    if (wid == 0) {
      int s = wsum[lane];
      #pragma unroll
      for (int o = 1; o < 32; o <<= 1) { int y = __shfl_up_sync(0xffffffffu, s, o); if (lane >= o) s += y; }
      wsum[lane] = s;
    }
    __syncthreads();
    int incl = x + (wid > 0 ? wsum[wid - 1] : 0);
    g_dwptr[tid] = incl - v;
  }
}

__global__ __launch_bounds__(256) void scatter_kernel(
    const int* __restrict__ ei, const float* __restrict__ ea)
{
  int e = blockIdx.x * 256 + threadIdx.x;
  if (e < EE) {
    int d = ei[EE + e];
    int pos = atomicAdd(&g_wptr[d], 1);
    g_src_sorted[pos] = ei[e];
    g_ea_sorted[pos] = ((const float4*)ea)[e];
  }
  if (e < NN) {
    int dd = g_deg[e]; if (dd > NBIN - 1) dd = NBIN - 1;
    int pos = atomicAdd(&g_dwptr[(NBIN - 1) - dd], 1);
    g_nodes_sorted[pos] = e;
  }
}

// ---------------- per-stage kernel 1: lean edge gather/accumulate ----------------
__global__ __launch_bounds__(ETHR) void edge_kernel(
    int pb,
    const float* __restrict__ W1m, const float* __restrict__ W2m,
    const float* __restrict__ b2m)
{
  __shared__ float sWea[4 * 64];
  __shared__ float sW2m[64 * 16];
  __shared__ float sb2m[16];
  __shared__ float sbuf[8][64];

  int tid = threadIdx.x;
  ((float4*)sW2m)[tid] = ((const float4*)W2m)[tid];       // 256 float4
  if (tid < 64) ((float4*)sWea)[tid] = ((const float4*)(W1m + 32 * 64))[tid];
  if (tid < 4)  ((float4*)sb2m)[tid] = ((const float4*)b2m)[tid];

  int w = tid >> 5, lane = tid & 31;
  int n = g_nodes_sorted[blockIdx.x * 8 + w];
  __syncthreads();

  const unsigned* __restrict__ U = (const unsigned*)&g_uv[pb][0];
  float v0 = g_v[n * 64 + lane];
  float v1 = g_v[n * 64 + 32 + lane];
  float wx0 = sWea[lane],        wx1 = sWea[32 + lane];
  float wy0 = sWea[64 + lane],   wy1 = sWea[96 + lane];
  float wz0 = sWea[128 + lane],  wz1 = sWea[160 + lane];
  float ww0 = sWea[192 + lane],  ww1 = sWea[224 + lane];

  float acc0 = 0.f, acc1 = 0.f;
  int beg = g_rowptr[n], end = g_rowptr[n + 1];

  int e = beg;
  for (; e + 4 <= end; e += 4) {
    int s0 = __ldg(g_src_sorted + e);
    int s1 = __ldg(g_src_sorted + e + 1);
    int s2 = __ldg(g_src_sorted + e + 2);
    int s3 = __ldg(g_src_sorted + e + 3);
    float4 a0 = __ldg(g_ea_sorted + e);
    float4 a1 = __ldg(g_ea_sorted + e + 1);
    float4 a2 = __ldg(g_ea_sorted + e + 2);
    float4 a3 = __ldg(g_ea_sorted + e + 3);
    unsigned u0 = __ldg(U + s0 * 32 + lane);
    unsigned u1 = __ldg(U + s1 * 32 + lane);
    unsigned u2 = __ldg(U + s2 * 32 + lane);
    unsigned u3 = __ldg(U + s3 * 32 + lane);
    {
      float2 uf = __half22float2(*reinterpret_cast<__half2*>(&u0));
      float t0 = uf.x + v0 + a0.x * wx0 + a0.y * wy0 + a0.z * wz0 + a0.w * ww0;
      float t1 = uf.y + v1 + a0.x * wx1 + a0.y * wy1 + a0.z * wz1 + a0.w * ww1;
      acc0 += tanha(t0); acc1 += tanha(t1);
    }
    {
      float2 uf = __half22float2(*reinterpret_cast<__half2*>(&u1));
      float t0 = uf.x + v0 + a1.x * wx0 + a1.y * wy0 + a1.z * wz0 + a1.w * ww0;
      float t1 = uf.y + v1 + a1.x * wx1 + a1.y * wy1 + a1.z * wz1 + a1.w * ww1;
      acc0 += tanha(t0); acc1 += tanha(t1);
    }
    {
      float2 uf = __half22float2(*reinterpret_cast<__half2*>(&u2));
      float t0 = uf.x + v0 + a2.x * wx0 + a2.y * wy0 + a2.z * wz0 + a2.w * ww0;
      float t1 = uf.y + v1 + a2.x * wx1 + a2.y * wy1 + a2.z * wz1 + a2.w * ww1;
      acc0 += tanha(t0); acc1 += tanha(t1);
    }
    {
      float2 uf = __half22float2(*reinterpret_cast<__half2*>(&u3));
      float t0 = uf.x + v0 + a3.x * wx0 + a3.y * wy0 + a3.z * wz0 + a3.w * ww0;
      float t1 = uf.y + v1 + a3.x * wx1 + a3.y * wy1 + a3.z * wz1 + a3.w * ww1;
      acc0 += tanha(t0); acc1 += tanha(t1);
    }
  }
  for (; e < end; e++) {
    int s0 = __ldg(g_src_sorted + e);
    float4 a0 = __ldg(g_ea_sorted + e);
    unsigned u0 = __ldg(U + s0 * 32 + lane);
    float2 uf = __half22float2(*reinterpret_cast<__half2*>(&u0));
    float t0 = uf.x + v0 + a0.x * wx0 + a0.y * wy0 + a0.z * wz0 + a0.w * ww0;
    float t1 = uf.y + v1 + a0.x * wx1 + a0.y * wy1 + a0.z * wz1 + a0.w * ww1;
    acc0 += tanha(t0); acc1 += tanha(t1);
  }

  // agg16 = hsum @ W2m + deg*b2m  (float4 broadcast of h-vector, 4 c per LDS)
  sbuf[w][lane] = acc0;
  sbuf[w][32 + lane] = acc1;
  __syncwarp();
  int j = lane & 15;
  int cbase = (lane < 16) ? 0 : 32;
  float p = 0.f;
  #pragma unroll
  for (int c4 = 0; c4 < 8; c4++) {
    float4 hv = ((const float4*)(sbuf[w] + cbase))[c4];
    p += hv.x * sW2m[(cbase + c4 * 4 + 0) * 16 + j];
    p += hv.y * sW2m[(cbase + c4 * 4 + 1) * 16 + j];
    p += hv.z * sW2m[(cbase + c4 * 4 + 2) * 16 + j];
    p += hv.w * sW2m[(cbase + c4 * 4 + 3) * 16 + j];
  }
  p += __shfl_xor_sync(0xffffffffu, p, 16);
  if (lane < 16) g_agg[n * 16 + j] = p + (float)(end - beg) * sb2m[j];
}

// ---------------- per-stage kernel 2: node MLP, 4 nodes per warp interleaved ----------------
template<int S>
__global__ __launch_bounds__(NTHRN) void node_kernel(
    int it, int sub, int outrow, int pb,
    const float* __restrict__ t,
    const float* __restrict__ W1m, const float* __restrict__ W1n,
    const float* __restrict__ W2n, const float* __restrict__ b2n,
    const float* __restrict__ b1m)
{
  __shared__ float2 sW1nxP[16 * 32];  // [i][lane] = (W1n[i][lane], W1n[i][lane+32])
  __shared__ float2 sW1naP[16 * 32];
  __shared__ float2 sW1mUP[16 * 32];  // W1m rows 0..15 (u)
  __shared__ float2 sW1mVP[16 * 32];  // W1m rows 16..31 (v)
  __shared__ float  sW2n[64 * 16];    // original layout (conflict-free reduce)
  __shared__ float  swt[64];
  __shared__ float  sb1m[64];
  __shared__ float  sb2n[16];
  __shared__ float  sxi[16][64];      // 4 nodes x 16 features
  __shared__ float  sagg[16][64];
  __shared__ float  sxin[16][64];
  __shared__ float  sbuf[16][256];    // tanh(h): 4 nodes x 64 ch

  int tid = threadIdx.x;
  {
    int i = tid;   // exactly 512 threads -> one pass
    int r = i >> 5, l = i & 31;
    sW1nxP[i] = make_float2(W1n[r * 64 + l],          W1n[r * 64 + 32 + l]);
    sW1naP[i] = make_float2(W1n[1024 + r * 64 + l],   W1n[1024 + r * 64 + 32 + l]);
    sW1mUP[i] = make_float2(W1m[r * 64 + l],          W1m[r * 64 + 32 + l]);
    sW1mVP[i] = make_float2(W1m[(16 + r) * 64 + l],   W1m[(16 + r) * 64 + 32 + l]);
  }
  for (int i = tid; i < 256; i += NTHRN) ((float4*)sW2n)[i] = ((const float4*)W2n)[i];
  if (tid < 16) ((float4*)swt)[tid] = ((const float4*)(W1n + 208 * 64))[tid];
  if (tid >= 16 && tid < 32) ((float4*)sb1m)[tid - 16] = ((const float4*)b1m)[tid - 16];
  if (tid >= 32 && tid < 36) ((float4*)sb2n)[tid - 32] = ((const float4*)b2n)[tid - 32];
  __syncthreads();

  int w = tid >> 5, lane = tid & 31;
  int j = lane & 15;
  int cbase = (lane < 16) ? 0 : 32;
  int nbase = (blockIdx.x * 16 + w) * 4;
  if (nbase >= NN) return;   // NN % 4 == 0 -> whole warp valid or whole warp idle

  float tA = __ldg(t + it), tB = __ldg(t + it + 1);
  float dti = (tB - tA) * 0.25f;
  float ti = tA + (float)sub * dti + c_C[S] * dti;
  constexpr int krow = (S < 5) ? S + 1 : 6;

  // stage xi/agg for 4 nodes (coalesced 64 floats each)
  sxi[w][lane]       = g_xi[nbase * 16 + lane];
  sxi[w][32 + lane]  = g_xi[nbase * 16 + 32 + lane];
  sagg[w][lane]      = g_agg[nbase * 16 + lane];
  sagg[w][32 + lane] = g_agg[nbase * 16 + 32 + lane];
  __syncwarp();

  // hidden layer for 4 nodes, weights shared
  float h0[4], h1[4];
  #pragma unroll
  for (int r = 0; r < 4; r++) {
    h0[r] = g_augproj[(nbase + r) * 64 + lane]      + ti * swt[lane];
    h1[r] = g_augproj[(nbase + r) * 64 + 32 + lane] + ti * swt[32 + lane];
  }
  #pragma unroll
  for (int i4 = 0; i4 < 4; i4++) {
    float4 X[4], A[4];
    #pragma unroll
    for (int r = 0; r < 4; r++) {
      X[r] = ((const float4*)(sxi[w]  + r * 16))[i4];
      A[r] = ((const float4*)(sagg[w] + r * 16))[i4];
    }
    #pragma unroll
    for (int k = 0; k < 4; k++) {
      int i = i4 * 4 + k;
      float2 wx = sW1nxP[i * 32 + lane];
      float2 wa = sW1naP[i * 32 + lane];
      #pragma unroll
      for (int r = 0; r < 4; r++) {
        float xv = ((const float*)&X[r])[k];
        float av = ((const float*)&A[r])[k];
        h0[r] += xv * wx.x + av * wa.x;
        h1[r] += xv * wx.y + av * wa.y;
      }
    }
  }
  #pragma unroll
  for (int r = 0; r < 4; r++) {
    sbuf[w][r * 64 + lane]      = tanha(h0[r]);
    sbuf[w][r * 64 + 32 + lane] = tanha(h1[r]);
  }
  __syncwarp();

  // output layer: o[r][j] = sum_c th[r][c] * W2n[c][j]
  float o[4] = {0.f, 0.f, 0.f, 0.f};
  #pragma unroll
  for (int c4 = 0; c4 < 8; c4++) {
    float4 B[4];
    #pragma unroll
    for (int r = 0; r < 4; r++)
      B[r] = ((const float4*)(sbuf[w] + r * 64 + cbase))[c4];
    #pragma unroll
    for (int k = 0; k < 4; k++) {
      float wv = sW2n[(cbase + c4 * 4 + k) * 16 + j];
      #pragma unroll
      for (int r = 0; r < 4; r++)
        o[r] += ((const float*)&B[r])[k] * wv;
    }
  }
  #pragma unroll
  for (int r = 0; r < 4; r++)
    o[r] += __shfl_xor_sync(0xffffffffu, o[r], 16);

  // epilogue: k store, xi_{S+1} combine per node
  if (lane < 16) {
    #pragma unroll
    for (int r = 0; r < 4; r++) {
      int idx = (nbase + r) * 16 + j;
      float kval = o[r] + sb2n[j];
      g_k[S][idx] = kval;
      float acc = c_coef[krow][S] * kval;
      #pragma unroll
      for (int jj = 0; jj < S; jj++) acc += c_coef[krow][jj] * g_k[jj][idx];
      float xv = g_x0[idx] + dti * acc;
      if (S == 5) {
        g_x0[idx] = xv;
        if (outrow >= 0) g_ys[outrow * NF + idx] = xv;
      }
      g_xi[idx] = xv;
      sxin[w][r * 16 + j] = xv;
    }
  }
  __syncwarp();

  // u/v projection for 4 nodes, weights shared
  float u0[4], u1[4], nv0[4], nv1[4];
  #pragma unroll
  for (int r = 0; r < 4; r++) {
    u0[r] = 0.f; u1[r] = 0.f;
    nv0[r] = sb1m[lane]; nv1[r] = sb1m[32 + lane];
  }
  #pragma unroll
  for (int i4 = 0; i4 < 4; i4++) {
    float4 X[4];
    #pragma unroll
    for (int r = 0; r < 4; r++)
      X[r] = ((const float4*)(sxin[w] + r * 16))[i4];
    #pragma unroll
    for (int k = 0; k < 4; k++) {
      int i = i4 * 4 + k;
      float2 wu = sW1mUP[i * 32 + lane];
      float2 wv = sW1mVP[i * 32 + lane];
      #pragma unroll
      for (int r = 0; r < 4; r++) {
        float xv = ((const float*)&X[r])[k];
        u0[r]  += xv * wu.x;  u1[r]  += xv * wu.y;
        nv0[r] += xv * wv.x;  nv1[r] += xv * wv.y;
      }
    }
  }
  #pragma unroll
  for (int r = 0; r < 4; r++) {
    int n = nbase + r;
    g_uv[pb ^ 1][n * 32 + lane] = __floats2half2_rn(u0[r], u1[r]);
    g_v[n * 64 + lane] = nv0[r];
    g_v[n * 64 + 32 + lane] = nv1[r];
  }
}

__global__ __launch_bounds__(256) void gather_out_kernel(
    const int* __restrict__ mask_idx, float* __restrict__ out)
{
  int idx = blockIdx.x * 256 + threadIdx.x;
  if (idx < TOUT * NF) {
    int row = idx / NF;
    int rem = idx - row * NF;
    out[idx] = g_ys[mask_idx[row] * NF + rem];
  }
}

// ---------------- launcher ----------------
extern "C" void kernel_launch(void* const* d_in, const int* in_sizes, int n_in,
                              void* d_out, int out_size)
{
  const float* x_hist   = (const float*)d_in[0];
  const float* x_mask   = (const float*)d_in[1];
  const int*   ei       = (const int*)d_in[2];
  const float* ea       = (const float*)d_in[3];
  const float* t        = (const float*)d_in[4];
  const int*   mask_idx = (const int*)d_in[5];
  const float* W1m = (const float*)d_in[6];
  const float* b1m = (const float*)d_in[7];
  const float* W2m = (const float*)d_in[8];
  const float* b2m = (const float*)d_in[9];
  const float* W1n = (const float*)d_in[10];
  const float* b1n = (const float*)d_in[11];
  const float* W2n = (const float*)d_in[12];
  const float* b2n = (const float*)d_in[13];
  float* out = (float*)d_out;

  init_kernel<<<(NN + 7) / 8, 256>>>(x_hist, W1m, b1m);
  augproj_kernel<<<NN / 4, 256>>>(x_hist, x_mask, W1n, b1n);
  hist_kernel<<<(EE + 255) / 256, 256>>>(ei);
  scan_kernel<<<1, 1024>>>();
  scatter_kernel<<<(EE + 255) / 256, 256>>>(ei, ea);

  int L = 0;
  for (int it = 0; it < TOUT; it++) {
    for (int sub = 0; sub < 4; sub++) {
      for (int s = 0; s < 6; s++) {
        int outrow = (s == 5 && sub == 3) ? it : -1;
        int pb = L & 1;
        edge_kernel<<<EBLK, ETHR>>>(pb, W1m, W2m, b2m);
        switch (s) {
          case 0: node_kernel<0><<<NBLKN, NTHRN>>>(it, sub, outrow, pb, t, W1m, W1n, W2n, b2n, b1m); break;
          case 1: node_kernel<1><<<NBLKN, NTHRN>>>(it, sub, outrow, pb, t, W1m, W1n, W2n, b2n, b1m); break;
          case 2: node_kernel<2><<<NBLKN, NTHRN>>>(it, sub, outrow, pb, t, W1m, W1n, W2n, b2n, b1m); break;
          case 3: node_kernel<3><<<NBLKN, NTHRN>>>(it, sub, outrow, pb, t, W1m, W1n, W2n, b2n, b1m); break;
          case 4: node_kernel<4><<<NBLKN, NTHRN>>>(it, sub, outrow, pb, t, W1m, W1n, W2n, b2n, b1m); break;
          case 5: node_kernel<5><<<NBLKN, NTHRN>>>(it, sub, outrow, pb, t, W1m, W1n, W2n, b2n, b1m); break;
        }
        L++;
      }
    }
  }

  gather_out_kernel<<<(TOUT * NF + 255) / 256, 256>>>(mask_idx, out);
}

// round 11
// speedup vs baseline: 1.0931x; 1.0931x over previous
#include <cuda_runtime.h>
#include <cuda_fp16.h>

#define NN 50000
#define FF 16
#define EE 800000
#define HH 64
#define TOUT 10
#define NF (NN*FF)

// ---------------- device state ----------------
__device__ float   g_x0[NF];
__device__ float   g_xi[NF];
__device__ float   g_k[6][NF];
__device__ __half2 g_uv[2][NN*32];   // packed u: (.x=ch lane, .y=ch lane+32), double-buffered
__device__ float   g_v[NN*HH];
__device__ float   g_augproj[NN*HH];
__device__ float   g_ys[TOUT*NF];
__device__ int     g_deg[NN];
__device__ int     g_rowptr[NN+1];
__device__ int     g_wptr[NN];
__device__ int     g_src_sorted[EE];
__device__ float4  g_ea_sorted[EE];

// DOPRI5 coefficients. Row 0 unused, rows 1..5 = A[0..4], row 6 = B.
__constant__ float c_coef[7][6] = {
  {0.f,0.f,0.f,0.f,0.f,0.f},
  {(float)(0.2), 0.f,0.f,0.f,0.f,0.f},
  {(float)(3.0/40.0), (float)(9.0/40.0), 0.f,0.f,0.f,0.f},
  {(float)(44.0/45.0), (float)(-56.0/15.0), (float)(32.0/9.0), 0.f,0.f,0.f},
  {(float)(19372.0/6561.0), (float)(-25360.0/2187.0), (float)(64448.0/6561.0), (float)(-212.0/729.0), 0.f,0.f},
  {(float)(9017.0/3168.0), (float)(-355.0/33.0), (float)(46732.0/5247.0), (float)(49.0/176.0), (float)(-5103.0/18656.0), 0.f},
  {(float)(35.0/384.0), 0.f, (float)(500.0/1113.0), (float)(125.0/192.0), (float)(-2187.0/6784.0), (float)(11.0/84.0)}
};
__constant__ float c_C[6] = {0.f, 0.2f, 0.3f, 0.8f, (float)(8.0/9.0), 1.f};

__device__ __forceinline__ float tanha(float x) {
  float r;
  asm("tanh.approx.f32 %0, %1;" : "=f"(r) : "f"(x));
  return r;
}

// ---------------- launch 1: combo = state init + augproj + u/v projection + deg zero ----------------
// 12500 blocks x 256 threads; 4 nodes per block. No histogram here (no race with zeroing).
__global__ __launch_bounds__(256) void combo_kernel(
    const float* __restrict__ xh, const float* __restrict__ xm,
    const float* __restrict__ W1m, const float* __restrict__ b1m,
    const float* __restrict__ W1n, const float* __restrict__ b1n)
{
  __shared__ float saug[4][176];
  __shared__ float sW[32 * 64];
  __shared__ float sxi[4][16];
  __shared__ float sb[64];
  int b = blockIdx.x;
  int tid = threadIdx.x;
  int gid = b * 256 + tid;
  if (gid < NN) g_deg[gid] = 0;          // re-zero degree histogram every launch
  int ln = tid >> 6;        // local node 0..3
  int ch = tid & 63;
  int n = b * 4 + ln;
  #pragma unroll
  for (int i = tid; i < 512; i += 256) ((float4*)sW)[i] = ((const float4*)W1m)[i];
  if (tid < 16) ((float4*)sb)[tid] = ((const float4*)b1m)[tid];
  if (ch < 16) {
    int f = ch;
    float xs[10], ms[10];
    float sm = 0.f, cm = 0.f;
    #pragma unroll
    for (int tt = 0; tt < 10; tt++) {
      xs[tt] = xh[(tt * NN + n) * FF + f];
      ms[tt] = xm[tt * NN + n];
      sm += xs[tt] * ms[tt];
      cm += ms[tt];
    }
    float cnt = fmaxf(cm, 1.0f);
    float mean = sm / cnt;
    float var = 0.f;
    #pragma unroll
    for (int tt = 0; tt < 10; tt++) { float d = xs[tt] - mean; var += d * d * ms[tt]; }
    var /= cnt;
    #pragma unroll
    for (int tt = 0; tt < 9; tt++)
      saug[ln][tt * 16 + f] = (xs[tt + 1] - xs[tt]) * (ms[tt + 1] * ms[tt]);
    saug[ln][144 + f] = mean;
    saug[ln][160 + f] = var;
    // initial ODE state
    int idx = n * 16 + f;
    float xv = xs[9];            // x_hist[-1]
    g_x0[idx] = xv;
    g_xi[idx] = xv;
    sxi[ln][f] = xv;
  }
  __syncthreads();
  // augproj = aug @ W1n[32:208] + b1n
  {
    float acc = b1n[ch];
    #pragma unroll 8
    for (int r = 0; r < 176; r++)
      acc += saug[ln][r] * W1n[(32 + r) * 64 + ch];
    g_augproj[n * 64 + ch] = acc;
  }
  // u/v projection from x0 into buffer 0
  if (ch < 32) {
    int lane = ch;
    float u0 = 0.f, u1 = 0.f;
    float v0 = sb[lane], v1 = sb[32 + lane];
    #pragma unroll
    for (int i = 0; i < 16; i++) {
      float xv = sxi[ln][i];
      u0 += xv * sW[i * 64 + lane];
      u1 += xv * sW[i * 64 + 32 + lane];
      v0 += xv * sW[(16 + i) * 64 + lane];
      v1 += xv * sW[(16 + i) * 64 + 32 + lane];
    }
    g_uv[0][n * 32 + lane] = __floats2half2_rn(u0, u1);
    g_v[n * 64 + lane] = v0;
    g_v[n * 64 + 32 + lane] = v1;
  }
}

// ---------------- launch 2: single-block histogram + rowptr scan ----------------
__global__ __launch_bounds__(1024) void histscan_kernel(const int* __restrict__ ei) {
  __shared__ int wsum[32];
  int tid = threadIdx.x, lane = tid & 31, wid = tid >> 5;
  // degree histogram (whole edge list from one block)
  for (int e = tid; e < EE; e += 1024)
    atomicAdd(&g_deg[ei[EE + e]], 1);
  __syncthreads();   // block-scope: all atomics visible to subsequent reads
  // exclusive/inclusive prefix scan of degrees
  int carry = 0;
  for (int base = 0; base < NN; base += 1024) {
    int i = base + tid;
    int v = (i < NN) ? g_deg[i] : 0;
    int x = v;
    #pragma unroll
    for (int o = 1; o < 32; o <<= 1) { int y = __shfl_up_sync(0xffffffffu, x, o); if (lane >= o) x += y; }
    if (lane == 31) wsum[wid] = x;
    __syncthreads();
    if (wid == 0) {
      int s = wsum[lane];
      #pragma unroll
      for (int o = 1; o < 32; o <<= 1) { int y = __shfl_up_sync(0xffffffffu, s, o); if (lane >= o) s += y; }
      wsum[lane] = s;
    }
    __syncthreads();
    int incl = x + carry + (wid > 0 ? wsum[wid - 1] : 0);
    if (i < NN) { g_rowptr[i + 1] = incl; g_wptr[i] = incl - v; }
    carry += wsum[31];
    __syncthreads();
  }
  if (tid == 0) g_rowptr[0] = 0;
}

// ---------------- launch 3: edge scatter into CSR ----------------
__global__ __launch_bounds__(256) void scatter_kernel(
    const int* __restrict__ ei, const float* __restrict__ ea)
{
  int e = blockIdx.x * 256 + threadIdx.x;
  if (e < EE) {
    int d = ei[EE + e];
    int pos = atomicAdd(&g_wptr[d], 1);
    g_src_sorted[pos] = ei[e];
    g_ea_sorted[pos] = ((const float4*)ea)[e];
  }
}

// ---------------- launch 4..243: fused per-stage kernel (R4-proven) ----------------
// warp per dst node: edge accumulate (CSR, u from half2 buffer pbuf) +
// node MLP -> k[s], then epilogue: xi_{s+1}, u/v projection into buffer pbuf^1.
__global__ __launch_bounds__(256) void edge_node_kernel(
    int s, int it, int sub, int outrow, int pbuf,
    const float* __restrict__ t,
    const float* __restrict__ W1m, const float* __restrict__ W2m,
    const float* __restrict__ b2m, const float* __restrict__ W1n,
    const float* __restrict__ W2n, const float* __restrict__ b2n,
    const float* __restrict__ b1m)
{
  __shared__ float sWea[4 * 64];
  __shared__ float sW2m[64 * 16];
  __shared__ float sW1nx[16 * 64];
  __shared__ float sW1na[16 * 64];
  __shared__ float sW2n[64 * 16];
  __shared__ float sW1m[32 * 64];
  __shared__ float swt[64];
  __shared__ float sb1m[64];
  __shared__ float sb2m[16], sb2n[16];
  __shared__ float sbuf[8][64];
  __shared__ float sxi[8][16];
  __shared__ float sagg[8][16];
  __shared__ float sxin[8][16];

  int tid = threadIdx.x;
  // stage weights (vectorized)
  if (tid < 64)  ((float4*)sWea)[tid] = ((const float4*)(W1m + 32 * 64))[tid];
  for (int i = tid; i < 256; i += 256) {
    ((float4*)sW2m)[i]  = ((const float4*)W2m)[i];
    ((float4*)sW1nx)[i] = ((const float4*)W1n)[i];
    ((float4*)sW1na)[i] = ((const float4*)(W1n + 1024))[i];
    ((float4*)sW2n)[i]  = ((const float4*)W2n)[i];
  }
  for (int i = tid; i < 512; i += 256) ((float4*)sW1m)[i] = ((const float4*)W1m)[i];
  if (tid < 16) ((float4*)swt)[tid]  = ((const float4*)(W1n + 208 * 64))[tid];
  if (tid >= 16 && tid < 32) ((float4*)sb1m)[tid - 16] = ((const float4*)b1m)[tid - 16];
  if (tid >= 32 && tid < 36) ((float4*)sb2m)[tid - 32] = ((const float4*)b2m)[tid - 32];
  if (tid >= 36 && tid < 40) ((float4*)sb2n)[tid - 36] = ((const float4*)b2n)[tid - 36];

  int w = tid >> 5, lane = tid & 31;
  int n = blockIdx.x * 8 + w;
  if (lane < 16) sxi[w][lane] = g_xi[n * 16 + lane];
  __syncthreads();

  float tA = t[it], tB = t[it + 1];
  float dti = (tB - tA) * 0.25f;
  float ti = tA + (float)sub * dti + c_C[s] * dti;

  const __half2* __restrict__ U = &g_uv[pbuf][0];
  float v0 = g_v[n * 64 + lane];
  float v1 = g_v[n * 64 + 32 + lane];
  float wx0 = sWea[lane],        wx1 = sWea[32 + lane];
  float wy0 = sWea[64 + lane],   wy1 = sWea[96 + lane];
  float wz0 = sWea[128 + lane],  wz1 = sWea[160 + lane];
  float ww0 = sWea[192 + lane],  ww1 = sWea[224 + lane];

  float acc0 = 0.f, acc1 = 0.f;
  int beg = g_rowptr[n], end = g_rowptr[n + 1];

  // 2-deep software pipeline over edges
  int e = beg;
  float4 eac = make_float4(0.f, 0.f, 0.f, 0.f); __half2 uhc = __float2half2_rn(0.f);
  if (e < end) {
    int srcc = g_src_sorted[e];
    eac = g_ea_sorted[e];
    uhc = U[srcc * 32 + lane];
  }
  for (; e < end; e++) {
    int e1 = e + 1;
    float4 ean = eac; __half2 uhn = uhc;
    if (e1 < end) {
      int srcn = g_src_sorted[e1];
      ean = g_ea_sorted[e1];
      uhn = U[srcn * 32 + lane];
    }
    float2 uf = __half22float2(uhc);
    float a0 = uf.x + v0;
    float a1 = uf.y + v1;
    a0 += eac.x * wx0 + eac.y * wy0 + eac.z * wz0 + eac.w * ww0;
    a1 += eac.x * wx1 + eac.y * wy1 + eac.z * wz1 + eac.w * ww1;
    acc0 += tanha(a0);
    acc1 += tanha(a1);
    eac = ean; uhc = uhn;
  }

  // agg16 = hsum @ W2m + deg*b2m
  sbuf[w][lane] = acc0;
  sbuf[w][32 + lane] = acc1;
  __syncwarp();
  int j = lane & 15;
  int cbase = (lane < 16) ? 0 : 32;
  float p = 0.f;
  #pragma unroll
  for (int c = 0; c < 32; c++) p += sbuf[w][cbase + c] * sW2m[(cbase + c) * 16 + j];
  p += __shfl_xor_sync(0xffffffffu, p, 16);
  float degf = (float)(end - beg);
  if (lane < 16) sagg[w][lane] = p + degf * sb2m[j];
  __syncwarp();

  // hidden = xi@W1n_x + agg@W1n_agg + aug_proj + ti*wt
  float h0 = g_augproj[n * 64 + lane]      + ti * swt[lane];
  float h1 = g_augproj[n * 64 + 32 + lane] + ti * swt[32 + lane];
  #pragma unroll
  for (int i = 0; i < 16; i++) {
    float xv = sxi[w][i], av = sagg[w][i];
    h0 += xv * sW1nx[i * 64 + lane]      + av * sW1na[i * 64 + lane];
    h1 += xv * sW1nx[i * 64 + 32 + lane] + av * sW1na[i * 64 + 32 + lane];
  }
  __syncwarp();
  sbuf[w][lane] = tanha(h0);
  sbuf[w][32 + lane] = tanha(h1);
  __syncwarp();

  float o = 0.f;
  #pragma unroll
  for (int c = 0; c < 32; c++) o += sbuf[w][cbase + c] * sW2n[(cbase + c) * 16 + j];
  o += __shfl_xor_sync(0xffffffffu, o, 16);
  float kval = o + sb2n[j];   // replicated on lane and lane+16

  // ---- fused epilogue: xi_{s+1} combine + u/v projection (buffer pbuf^1) ----
  if (lane < 16) {
    int idx = n * 16 + j;
    g_k[s][idx] = kval;
    int row = (s < 5) ? s + 1 : 6;
    float acc = c_coef[row][s] * kval;
    #pragma unroll
    for (int jj = 0; jj < 5; jj++) {
      if (jj < s) acc += c_coef[row][jj] * g_k[jj][idx];
    }
    float xv = g_x0[idx] + dti * acc;
    if (s == 5) {
      g_x0[idx] = xv;
      if (outrow >= 0) g_ys[outrow * NF + idx] = xv;
    }
    g_xi[idx] = xv;
    sxin[w][j] = xv;
  }
  __syncwarp();

  float u0 = 0.f, u1 = 0.f;
  float nv0 = sb1m[lane], nv1 = sb1m[32 + lane];
  #pragma unroll
  for (int i = 0; i < 16; i++) {
    float xv = sxin[w][i];
    u0  += xv * sW1m[i * 64 + lane];
    u1  += xv * sW1m[i * 64 + 32 + lane];
    nv0 += xv * sW1m[(16 + i) * 64 + lane];
    nv1 += xv * sW1m[(16 + i) * 64 + 32 + lane];
  }
  g_uv[pbuf ^ 1][n * 32 + lane] = __floats2half2_rn(u0, u1);
  g_v[n * 64 + lane] = nv0;
  g_v[n * 64 + 32 + lane] = nv1;
}

__global__ __launch_bounds__(256) void gather_out_kernel(
    const int* __restrict__ mask_idx, float* __restrict__ out)
{
  int idx = blockIdx.x * 256 + threadIdx.x;
  if (idx < TOUT * NF) {
    int row = idx / NF;
    int rem = idx - row * NF;
    out[idx] = g_ys[mask_idx[row] * NF + rem];
  }
}

// ---------------- launcher ----------------
extern "C" void kernel_launch(void* const* d_in, const int* in_sizes, int n_in,
                              void* d_out, int out_size)
{
  const float* x_hist   = (const float*)d_in[0];
  const float* x_mask   = (const float*)d_in[1];
  const int*   ei       = (const int*)d_in[2];
  const float* ea       = (const float*)d_in[3];
  const float* t        = (const float*)d_in[4];
  const int*   mask_idx = (const int*)d_in[5];
  const float* W1m = (const float*)d_in[6];
  const float* b1m = (const float*)d_in[7];
  const float* W2m = (const float*)d_in[8];
  const float* b2m = (const float*)d_in[9];
  const float* W1n = (const float*)d_in[10];
  const float* b1n = (const float*)d_in[11];
  const float* W2n = (const float*)d_in[12];
  const float* b2n = (const float*)d_in[13];
  float* out = (float*)d_out;

  // exactly 3 setup launches -> the 4th process launch is edge_node_kernel (ncu target)
  combo_kernel<<<NN / 4, 256>>>(x_hist, x_mask, W1m, b1m, W1n, b1n);   // 1
  histscan_kernel<<<1, 1024>>>(ei);                                     // 2
  scatter_kernel<<<(EE + 255) / 256, 256>>>(ei, ea);                    // 3

  int L = 0;
  for (int it = 0; it < TOUT; it++) {
    for (int sub = 0; sub < 4; sub++) {
      for (int s = 0; s < 6; s++) {
        int outrow = (s == 5 && sub == 3) ? it : -1;
        edge_node_kernel<<<NN / 8, 256>>>(s, it, sub, outrow, L & 1,
                                          t, W1m, W2m, b2m, W1n, W2n, b2n, b1m);
        L++;
      }
    }
  }

  gather_out_kernel<<<(TOUT * NF + 255) / 256, 256>>>(mask_idx, out);
}

// round 12
// speedup vs baseline: 1.4235x; 1.3023x over previous
#include <cuda_runtime.h>
#include <cuda_fp16.h>

#define NN 50000
#define FF 16
#define EE 800000
#define HH 64
#define TOUT 10
#define NF (NN*FF)

// ---------------- device state ----------------
__device__ float   g_x0[NF];
__device__ float   g_xi[NF];
__device__ float   g_k[6][NF];
__device__ __half2 g_uv[2][NN*32];   // packed u: (.x=ch lane, .y=ch lane+32), double-buffered
__device__ float   g_v[NN*HH];
__device__ float   g_augproj[NN*HH];
__device__ float   g_ys[TOUT*NF];
__device__ int     g_deg[NN];
__device__ int     g_rowptr[NN+1];
__device__ int     g_wptr[NN];
__device__ int     g_src_sorted[EE];
__device__ float4  g_ea_sorted[EE];

// DOPRI5 coefficients. Row 0 unused, rows 1..5 = A[0..4], row 6 = B.
__constant__ float c_coef[7][6] = {
  {0.f,0.f,0.f,0.f,0.f,0.f},
  {(float)(0.2), 0.f,0.f,0.f,0.f,0.f},
  {(float)(3.0/40.0), (float)(9.0/40.0), 0.f,0.f,0.f,0.f},
  {(float)(44.0/45.0), (float)(-56.0/15.0), (float)(32.0/9.0), 0.f,0.f,0.f},
  {(float)(19372.0/6561.0), (float)(-25360.0/2187.0), (float)(64448.0/6561.0), (float)(-212.0/729.0), 0.f,0.f},
  {(float)(9017.0/3168.0), (float)(-355.0/33.0), (float)(46732.0/5247.0), (float)(49.0/176.0), (float)(-5103.0/18656.0), 0.f},
  {(float)(35.0/384.0), 0.f, (float)(500.0/1113.0), (float)(125.0/192.0), (float)(-2187.0/6784.0), (float)(11.0/84.0)}
};
__constant__ float c_C[6] = {0.f, 0.2f, 0.3f, 0.8f, (float)(8.0/9.0), 1.f};

__device__ __forceinline__ float tanha(float x) {
  float r;
  asm("tanh.approx.f32 %0, %1;" : "=f"(r) : "f"(x));
  return r;
}

// ---------------- launch 1: combo = state init + augproj + u/v projection + deg zero ----------------
__global__ __launch_bounds__(256) void combo_kernel(
    const float* __restrict__ xh, const float* __restrict__ xm,
    const float* __restrict__ W1m, const float* __restrict__ b1m,
    const float* __restrict__ W1n, const float* __restrict__ b1n)
{
  __shared__ float saug[4][176];
  __shared__ float sW[32 * 64];
  __shared__ float sxi[4][16];
  __shared__ float sb[64];
  int b = blockIdx.x;
  int tid = threadIdx.x;
  int gid = b * 256 + tid;
  if (gid < NN) g_deg[gid] = 0;
  int ln = tid >> 6;
  int ch = tid & 63;
  int n = b * 4 + ln;
  #pragma unroll
  for (int i = tid; i < 512; i += 256) ((float4*)sW)[i] = ((const float4*)W1m)[i];
  if (tid < 16) ((float4*)sb)[tid] = ((const float4*)b1m)[tid];
  if (ch < 16) {
    int f = ch;
    float xs[10], ms[10];
    float sm = 0.f, cm = 0.f;
    #pragma unroll
    for (int tt = 0; tt < 10; tt++) {
      xs[tt] = xh[(tt * NN + n) * FF + f];
      ms[tt] = xm[tt * NN + n];
      sm += xs[tt] * ms[tt];
      cm += ms[tt];
    }
    float cnt = fmaxf(cm, 1.0f);
    float mean = sm / cnt;
    float var = 0.f;
    #pragma unroll
    for (int tt = 0; tt < 10; tt++) { float d = xs[tt] - mean; var += d * d * ms[tt]; }
    var /= cnt;
    #pragma unroll
    for (int tt = 0; tt < 9; tt++)
      saug[ln][tt * 16 + f] = (xs[tt + 1] - xs[tt]) * (ms[tt + 1] * ms[tt]);
    saug[ln][144 + f] = mean;
    saug[ln][160 + f] = var;
    int idx = n * 16 + f;
    float xv = xs[9];
    g_x0[idx] = xv;
    g_xi[idx] = xv;
    sxi[ln][f] = xv;
  }
  __syncthreads();
  {
    float acc = b1n[ch];
    #pragma unroll 8
    for (int r = 0; r < 176; r++)
      acc += saug[ln][r] * W1n[(32 + r) * 64 + ch];
    g_augproj[n * 64 + ch] = acc;
  }
  if (ch < 32) {
    int lane = ch;
    float u0 = 0.f, u1 = 0.f;
    float v0 = sb[lane], v1 = sb[32 + lane];
    #pragma unroll
    for (int i = 0; i < 16; i++) {
      float xv = sxi[ln][i];
      u0 += xv * sW[i * 64 + lane];
      u1 += xv * sW[i * 64 + 32 + lane];
      v0 += xv * sW[(16 + i) * 64 + lane];
      v1 += xv * sW[(16 + i) * 64 + 32 + lane];
    }
    g_uv[0][n * 32 + lane] = __floats2half2_rn(u0, u1);
    g_v[n * 64 + lane] = v0;
    g_v[n * 64 + 32 + lane] = v1;
  }
}

// ---------------- launch 2: single-block histogram + rowptr scan ----------------
__global__ __launch_bounds__(1024) void histscan_kernel(const int* __restrict__ ei) {
  __shared__ int wsum[32];
  int tid = threadIdx.x, lane = tid & 31, wid = tid >> 5;
  for (int e = tid; e < EE; e += 1024)
    atomicAdd(&g_deg[ei[EE + e]], 1);
  __syncthreads();
  int carry = 0;
  for (int base = 0; base < NN; base += 1024) {
    int i = base + tid;
    int v = (i < NN) ? g_deg[i] : 0;
    int x = v;
    #pragma unroll
    for (int o = 1; o < 32; o <<= 1) { int y = __shfl_up_sync(0xffffffffu, x, o); if (lane >= o) x += y; }
    if (lane == 31) wsum[wid] = x;
    __syncthreads();
    if (wid == 0) {
      int s = wsum[lane];
      #pragma unroll
      for (int o = 1; o < 32; o <<= 1) { int y = __shfl_up_sync(0xffffffffu, s, o); if (lane >= o) s += y; }
      wsum[lane] = s;
    }
    __syncthreads();
    int incl = x + carry + (wid > 0 ? wsum[wid - 1] : 0);
    if (i < NN) { g_rowptr[i + 1] = incl; g_wptr[i] = incl - v; }
    carry += wsum[31];
    __syncthreads();
  }
  if (tid == 0) g_rowptr[0] = 0;
}

// ---------------- launch 3: edge scatter into CSR ----------------
__global__ __launch_bounds__(256) void scatter_kernel(
    const int* __restrict__ ei, const float* __restrict__ ea)
{
  int e = blockIdx.x * 256 + threadIdx.x;
  if (e < EE) {
    int d = ei[EE + e];
    int pos = atomicAdd(&g_wptr[d], 1);
    g_src_sorted[pos] = ei[e];
    g_ea_sorted[pos] = ((const float4*)ea)[e];
  }
}

// ---------------- launch 4..243: fused per-stage kernel, 2 nodes per warp ----------------
__global__ __launch_bounds__(256) void edge_node_kernel(
    int s, int it, int sub, int outrow, int pbuf,
    const float* __restrict__ t,
    const float* __restrict__ W1m, const float* __restrict__ W2m,
    const float* __restrict__ b2m, const float* __restrict__ W1n,
    const float* __restrict__ W2n, const float* __restrict__ b2n,
    const float* __restrict__ b1m)
{
  __shared__ float sWea[4 * 64];
  __shared__ float sW2m[64 * 16];
  __shared__ float sW1nx[16 * 64];
  __shared__ float sW1na[16 * 64];
  __shared__ float sW2n[64 * 16];
  __shared__ float sW1m[32 * 64];
  __shared__ float swt[64];
  __shared__ float sb1m[64];
  __shared__ float sb2m[16], sb2n[16];
  __shared__ float sbuf[8][128];   // 2 nodes x 64 ch per warp
  __shared__ float sxi[8][32];     // 2 nodes x 16
  __shared__ float sagg[8][32];
  __shared__ float sxin[8][32];

  int tid = threadIdx.x;
  if (tid < 64)  ((float4*)sWea)[tid] = ((const float4*)(W1m + 32 * 64))[tid];
  for (int i = tid; i < 256; i += 256) {
    ((float4*)sW2m)[i]  = ((const float4*)W2m)[i];
    ((float4*)sW1nx)[i] = ((const float4*)W1n)[i];
    ((float4*)sW1na)[i] = ((const float4*)(W1n + 1024))[i];
    ((float4*)sW2n)[i]  = ((const float4*)W2n)[i];
  }
  for (int i = tid; i < 512; i += 256) ((float4*)sW1m)[i] = ((const float4*)W1m)[i];
  if (tid < 16) ((float4*)swt)[tid]  = ((const float4*)(W1n + 208 * 64))[tid];
  if (tid >= 16 && tid < 32) ((float4*)sb1m)[tid - 16] = ((const float4*)b1m)[tid - 16];
  if (tid >= 32 && tid < 36) ((float4*)sb2m)[tid - 32] = ((const float4*)b2m)[tid - 32];
  if (tid >= 36 && tid < 40) ((float4*)sb2n)[tid - 36] = ((const float4*)b2n)[tid - 36];

  int w = tid >> 5, lane = tid & 31;
  int n0 = (blockIdx.x * 8 + w) * 2;   // warp owns nodes n0, n0+1 (contiguous)
  int n1 = n0 + 1;
  sxi[w][lane] = g_xi[n0 * 16 + lane];   // 32 floats = both nodes' xi, coalesced
  __syncthreads();

  float tA = t[it], tB = t[it + 1];
  float dti = (tB - tA) * 0.25f;
  float ti = tA + (float)sub * dti + c_C[s] * dti;

  const __half2* __restrict__ U = &g_uv[pbuf][0];
  float v0a = g_v[n0 * 64 + lane], v1a = g_v[n0 * 64 + 32 + lane];
  float v0b = g_v[n1 * 64 + lane], v1b = g_v[n1 * 64 + 32 + lane];
  float wx0 = sWea[lane],        wx1 = sWea[32 + lane];
  float wy0 = sWea[64 + lane],   wy1 = sWea[96 + lane];
  float wz0 = sWea[128 + lane],  wz1 = sWea[160 + lane];
  float ww0 = sWea[192 + lane],  ww1 = sWea[224 + lane];

  int bega = g_rowptr[n0];
  int begb = g_rowptr[n0 + 1];
  int endb = g_rowptr[n0 + 2];

  float acc0a = 0.f, acc1a = 0.f, acc0b = 0.f, acc1b = 0.f;

  // ---- edge loop node0 (2-deep pipeline) ----
  {
    int e = bega, end = begb;
    float4 eac = make_float4(0.f, 0.f, 0.f, 0.f); __half2 uhc = __float2half2_rn(0.f);
    if (e < end) {
      int srcc = g_src_sorted[e];
      eac = g_ea_sorted[e];
      uhc = U[srcc * 32 + lane];
    }
    for (; e < end; e++) {
      int e1 = e + 1;
      float4 ean = eac; __half2 uhn = uhc;
      if (e1 < end) {
        int srcn = g_src_sorted[e1];
        ean = g_ea_sorted[e1];
        uhn = U[srcn * 32 + lane];
      }
      float2 uf = __half22float2(uhc);
      float a0 = uf.x + v0a;
      float a1 = uf.y + v1a;
      a0 += eac.x * wx0 + eac.y * wy0 + eac.z * wz0 + eac.w * ww0;
      a1 += eac.x * wx1 + eac.y * wy1 + eac.z * wz1 + eac.w * ww1;
      acc0a += tanha(a0);
      acc1a += tanha(a1);
      eac = ean; uhc = uhn;
    }
  }
  // ---- edge loop node1 ----
  {
    int e = begb, end = endb;
    float4 eac = make_float4(0.f, 0.f, 0.f, 0.f); __half2 uhc = __float2half2_rn(0.f);
    if (e < end) {
      int srcc = g_src_sorted[e];
      eac = g_ea_sorted[e];
      uhc = U[srcc * 32 + lane];
    }
    for (; e < end; e++) {
      int e1 = e + 1;
      float4 ean = eac; __half2 uhn = uhc;
      if (e1 < end) {
        int srcn = g_src_sorted[e1];
        ean = g_ea_sorted[e1];
        uhn = U[srcn * 32 + lane];
      }
      float2 uf = __half22float2(uhc);
      float a0 = uf.x + v0b;
      float a1 = uf.y + v1b;
      a0 += eac.x * wx0 + eac.y * wy0 + eac.z * wz0 + eac.w * ww0;
      a1 += eac.x * wx1 + eac.y * wy1 + eac.z * wz1 + eac.w * ww1;
      acc0b += tanha(a0);
      acc1b += tanha(a1);
      eac = ean; uhc = uhn;
    }
  }

  // ---- agg for both nodes: shared W2m reads, float4 h-vector broadcasts ----
  sbuf[w][lane]      = acc0a;
  sbuf[w][32 + lane] = acc1a;
  sbuf[w][64 + lane] = acc0b;
  sbuf[w][96 + lane] = acc1b;
  __syncwarp();
  int j = lane & 15;
  int cbase = (lane < 16) ? 0 : 32;
  float pa = 0.f, pb = 0.f;
  #pragma unroll
  for (int c4 = 0; c4 < 8; c4++) {
    float4 ha = ((const float4*)(sbuf[w] + cbase))[c4];
    float4 hb = ((const float4*)(sbuf[w] + 64 + cbase))[c4];
    float w0 = sW2m[(cbase + c4 * 4 + 0) * 16 + j];
    float w1 = sW2m[(cbase + c4 * 4 + 1) * 16 + j];
    float w2 = sW2m[(cbase + c4 * 4 + 2) * 16 + j];
    float w3 = sW2m[(cbase + c4 * 4 + 3) * 16 + j];
    pa += ha.x * w0 + ha.y * w1 + ha.z * w2 + ha.w * w3;
    pb += hb.x * w0 + hb.y * w1 + hb.z * w2 + hb.w * w3;
  }
  pa += __shfl_xor_sync(0xffffffffu, pa, 16);
  pb += __shfl_xor_sync(0xffffffffu, pb, 16);
  {
    int r = lane >> 4;
    float deg = (float)(r ? (endb - begb) : (begb - bega));
    float pv = r ? pb : pa;
    sagg[w][lane] = pv + deg * sb2m[j];   // lane = r*16+j
  }
  __syncwarp();

  // ---- hidden layer for both nodes, shared weight reads ----
  float h0a = g_augproj[n0 * 64 + lane]      + ti * swt[lane];
  float h1a = g_augproj[n0 * 64 + 32 + lane] + ti * swt[32 + lane];
  float h0b = g_augproj[n1 * 64 + lane]      + ti * swt[lane];
  float h1b = g_augproj[n1 * 64 + 32 + lane] + ti * swt[32 + lane];
  #pragma unroll
  for (int i = 0; i < 16; i++) {
    float wxa = sW1nx[i * 64 + lane], wxb = sW1nx[i * 64 + 32 + lane];
    float waa = sW1na[i * 64 + lane], wab = sW1na[i * 64 + 32 + lane];
    float xva = sxi[w][i],  xvb = sxi[w][16 + i];
    float ava = sagg[w][i], avb = sagg[w][16 + i];
    h0a += xva * wxa + ava * waa;
    h1a += xva * wxb + ava * wab;
    h0b += xvb * wxa + avb * waa;
    h1b += xvb * wxb + avb * wab;
  }
  __syncwarp();
  sbuf[w][lane]      = tanha(h0a);
  sbuf[w][32 + lane] = tanha(h1a);
  sbuf[w][64 + lane] = tanha(h0b);
  sbuf[w][96 + lane] = tanha(h1b);
  __syncwarp();

  // ---- output layer for both nodes ----
  float oa = 0.f, ob = 0.f;
  #pragma unroll
  for (int c4 = 0; c4 < 8; c4++) {
    float4 ha = ((const float4*)(sbuf[w] + cbase))[c4];
    float4 hb = ((const float4*)(sbuf[w] + 64 + cbase))[c4];
    float w0 = sW2n[(cbase + c4 * 4 + 0) * 16 + j];
    float w1 = sW2n[(cbase + c4 * 4 + 1) * 16 + j];
    float w2 = sW2n[(cbase + c4 * 4 + 2) * 16 + j];
    float w3 = sW2n[(cbase + c4 * 4 + 3) * 16 + j];
    oa += ha.x * w0 + ha.y * w1 + ha.z * w2 + ha.w * w3;
    ob += hb.x * w0 + hb.y * w1 + hb.z * w2 + hb.w * w3;
  }
  oa += __shfl_xor_sync(0xffffffffu, oa, 16);
  ob += __shfl_xor_sync(0xffffffffu, ob, 16);

  // ---- epilogue: all 32 lanes active; lane = r*16 + j handles (node n0+r, col j) ----
  {
    int r = lane >> 4;
    int idx = (n0 + r) * 16 + j;            // lanes cover 32 contiguous floats
    float kval = (r ? ob : oa) + sb2n[j];
    g_k[s][idx] = kval;
    int row = (s < 5) ? s + 1 : 6;
    float acc = c_coef[row][s] * kval;
    #pragma unroll
    for (int jj = 0; jj < 5; jj++) {
      if (jj < s) acc += c_coef[row][jj] * g_k[jj][idx];
    }
    float xv = g_x0[idx] + dti * acc;
    if (s == 5) {
      g_x0[idx] = xv;
      if (outrow >= 0) g_ys[outrow * NF + idx] = xv;
    }
    g_xi[idx] = xv;
    sxin[w][lane] = xv;                      // lane = r*16+j
  }
  __syncwarp();

  // ---- u/v projection for both nodes, shared weight reads ----
  float u0a = 0.f, u1a = 0.f, u0b = 0.f, u1b = 0.f;
  float nv0a = sb1m[lane], nv1a = sb1m[32 + lane];
  float nv0b = nv0a, nv1b = nv1a;
  #pragma unroll
  for (int i = 0; i < 16; i++) {
    float wu0 = sW1m[i * 64 + lane],        wu1 = sW1m[i * 64 + 32 + lane];
    float wv0 = sW1m[(16 + i) * 64 + lane], wv1 = sW1m[(16 + i) * 64 + 32 + lane];
    float xa = sxin[w][i], xb = sxin[w][16 + i];
    u0a  += xa * wu0;  u1a  += xa * wu1;
    nv0a += xa * wv0;  nv1a += xa * wv1;
    u0b  += xb * wu0;  u1b  += xb * wu1;
    nv0b += xb * wv0;  nv1b += xb * wv1;
  }
  g_uv[pbuf ^ 1][n0 * 32 + lane] = __floats2half2_rn(u0a, u1a);
  g_uv[pbuf ^ 1][n1 * 32 + lane] = __floats2half2_rn(u0b, u1b);
  g_v[n0 * 64 + lane] = nv0a;
  g_v[n0 * 64 + 32 + lane] = nv1a;
  g_v[n1 * 64 + lane] = nv0b;
  g_v[n1 * 64 + 32 + lane] = nv1b;
}

__global__ __launch_bounds__(256) void gather_out_kernel(
    const int* __restrict__ mask_idx, float* __restrict__ out)
{
  int idx = blockIdx.x * 256 + threadIdx.x;
  if (idx < TOUT * NF) {
    int row = idx / NF;
    int rem = idx - row * NF;
    out[idx] = g_ys[mask_idx[row] * NF + rem];
  }
}

// ---------------- launcher ----------------
extern "C" void kernel_launch(void* const* d_in, const int* in_sizes, int n_in,
                              void* d_out, int out_size)
{
  const float* x_hist   = (const float*)d_in[0];
  const float* x_mask   = (const float*)d_in[1];
  const int*   ei       = (const int*)d_in[2];
  const float* ea       = (const float*)d_in[3];
  const float* t        = (const float*)d_in[4];
  const int*   mask_idx = (const int*)d_in[5];
  const float* W1m = (const float*)d_in[6];
  const float* b1m = (const float*)d_in[7];
  const float* W2m = (const float*)d_in[8];
  const float* b2m = (const float*)d_in[9];
  const float* W1n = (const float*)d_in[10];
  const float* b1n = (const float*)d_in[11];
  const float* W2n = (const float*)d_in[12];
  const float* b2n = (const float*)d_in[13];
  float* out = (float*)d_out;

  // exactly 3 setup launches -> the 4th process launch is edge_node_kernel (ncu target)
  combo_kernel<<<NN / 4, 256>>>(x_hist, x_mask, W1m, b1m, W1n, b1n);   // 1
  histscan_kernel<<<1, 1024>>>(ei);                                     // 2
  scatter_kernel<<<(EE + 255) / 256, 256>>>(ei, ea);                    // 3

  int L = 0;
  for (int it = 0; it < TOUT; it++) {
    for (int sub = 0; sub < 4; sub++) {
      for (int s = 0; s < 6; s++) {
        int outrow = (s == 5 && sub == 3) ? it : -1;
        edge_node_kernel<<<NN / 16, 256>>>(s, it, sub, outrow, L & 1,
                                           t, W1m, W2m, b2m, W1n, W2n, b2n, b1m);
        L++;
      }
    }
  }

  gather_out_kernel<<<(TOUT * NF + 255) / 256, 256>>>(mask_idx, out);
}